// round 15
// baseline (speedup 1.0000x reference)
#include <cuda_runtime.h>
#include <cuda_bf16.h>

// out[b,s,d] = in[b,s,d] + pe(s,d)
//   pe(s,d) = sin(s * f(d)) if d even else cos(s * f(d)),  f(d) = 10000^(-2d/D)
//
// B=8, S=4096, D=1024, fp32. 268 MB/launch. Sustained BW ceiling reached:
// full-width-prefetch family benches {45.57, 45.63, 47.07} vs phase-split
// family {47.6+}; bench noise ~±1.5us (R14 replication of R12).
// R15 = R12 with the last scheduling wart removed: the prefetch's
// `if (more)` guard (predicated LDGs or BSSY/BSYNC region per iteration)
// is replaced by an UNCONDITIONAL prefetch with clamped row index
// (min(snext, S-1)) -> straight-line loads every iteration. Cost: one
// discarded row-load on each block's final iteration (+0.05% bytes).
// All else byte-identical to R12: grid 592, LB(256,3), .cs both ways,
// float4/256-thread map, rotation copy kept.

constexpr int D    = 1024;
constexpr int S    = 4096;
constexpr int B    = 8;
constexpr int TPB  = D / 4;       // 256 threads, one float4 of d each
constexpr int GRID = 4 * 148;     // 592 blocks, grid-stride over s
constexpr int SD   = S * TPB;     // float4 stride between batches

__global__ __launch_bounds__(TPB, 3)
void pe_add_kernel(const float4* __restrict__ in, float4* __restrict__ out) {
    const int d4 = threadIdx.x;
    const int d  = d4 * 4;

    // f(d+j) = exp2( -(d+j) * 2*log2(10000)/1024 ), row-independent
    const float c = -2.0f * 13.287712379549449f / (float)D;
    const float f0 = exp2f(c * (float)(d + 0));
    const float f1 = exp2f(c * (float)(d + 1));
    const float f2 = exp2f(c * (float)(d + 2));
    const float f3 = exp2f(c * (float)(d + 3));

    int s   = blockIdx.x;
    int row = s * TPB + d4;

    // Prologue: entire row s (all 8 batches) in flight
    float4 A[B];
    #pragma unroll
    for (int b = 0; b < B; ++b) A[b] = __ldcs(&in[b * SD + row]);

    while (true) {
        const int snext = s + GRID;
        const bool more = snext < S;
        // Clamped prefetch row: unconditional loads (no predicate/branch in
        // the hot loop); final iteration re-reads a dead row (discarded).
        const int sclmp = more ? snext : (S - 1);
        const int rown  = sclmp * TPB + d4;

        // Prefetch FIRST: 8 loads issued before any MUFU/store work, so
        // read-issue never pauses at the top of the iteration and the MUFU
        // latency below hides under the in-flight loads.
        float4 N[B];
        #pragma unroll
        for (int b = 0; b < B; ++b) N[b] = __ldcs(&in[b * SD + rown]);

        const float fs = (float)s;
        float4 pe;                      // d%4==0: x,z even (sin); y,w odd (cos)
        pe.x = __sinf(fs * f0);
        pe.y = __cosf(fs * f1);
        pe.z = __sinf(fs * f2);
        pe.w = __cosf(fs * f3);

        // Store row s (depends only on A, already landed, and pe)
        #pragma unroll
        for (int b = 0; b < B; ++b) {
            float4 o;
            o.x = A[b].x + pe.x; o.y = A[b].y + pe.y;
            o.z = A[b].z + pe.z; o.w = A[b].w + pe.w;
            __stcs(&out[b * SD + row], o);
        }

        if (!more) break;
        #pragma unroll
        for (int b = 0; b < B; ++b) A[b] = N[b];
        s = snext;
        row = rown;
    }
}

extern "C" void kernel_launch(void* const* d_in, const int* in_sizes, int n_in,
                              void* d_out, int out_size) {
    (void)in_sizes; (void)n_in; (void)out_size;
    const float4* in  = (const float4*)d_in[0];
    float4*       out = (float4*)d_out;
    pe_add_kernel<<<GRID, TPB>>>(in, out);
}

// round 16
// speedup vs baseline: 1.0372x; 1.0372x over previous
#include <cuda_runtime.h>
#include <cuda_bf16.h>

// out[b,s,d] = in[b,s,d] + pe(s,d)
//   pe(s,d) = sin(s * f(d)) if d even else cos(s * f(d)),  f(d) = 10000^(-2d/D)
//
// B=8, S=4096, D=1024, fp32. 268 MB/launch -> sustained-BW-bound.
// FINAL (= R12 exactly, best measured: bench 45.568us, ncu 38.98us/69.4% DRAM).
// Converged configuration after 15 rounds:
//   - float4 / 256-thread d-mapping (8-float and scalar maps cost +6us: R6/R8)
//   - full-width software pipeline: ALL 8 next-row loads issued at the TOP of
//     the loop body, before MUFU pe + store burst (read-issue continuity was
//     the only SM-side mechanism that beat the 47.6us plateau: R10)
//   - rotation copy A<-N kept; ping-pong/clamp/grid-444 variants all degrade
//     ptxas's schedule (R11, R13, R15 falsified)
//   - .cs streaming loads AND stores (evict_last pinning falsified R6/R8;
//     default LRU falsified R9)
//   - grid 592 = 4*148, LB(256,3): 3 resident/SM + back-fill tail
//   - exp2f-based inv_freq hoisted per-thread; __sinf/__cosf per (s,d) only,
//     reused across the 8-batch dimension (rel_err 2.5e-05 << 1e-3)

constexpr int D    = 1024;
constexpr int S    = 4096;
constexpr int B    = 8;
constexpr int TPB  = D / 4;       // 256 threads, one float4 of d each
constexpr int GRID = 4 * 148;     // 592 blocks, grid-stride over s
constexpr int SD   = S * TPB;     // float4 stride between batches

__global__ __launch_bounds__(TPB, 3)
void pe_add_kernel(const float4* __restrict__ in, float4* __restrict__ out) {
    const int d4 = threadIdx.x;
    const int d  = d4 * 4;

    // f(d+j) = exp2( -(d+j) * 2*log2(10000)/1024 ), row-independent
    const float c = -2.0f * 13.287712379549449f / (float)D;
    const float f0 = exp2f(c * (float)(d + 0));
    const float f1 = exp2f(c * (float)(d + 1));
    const float f2 = exp2f(c * (float)(d + 2));
    const float f3 = exp2f(c * (float)(d + 3));

    int s   = blockIdx.x;
    int row = s * TPB + d4;

    // Prologue: entire row s (all 8 batches) in flight
    float4 A[B];
    #pragma unroll
    for (int b = 0; b < B; ++b) A[b] = __ldcs(&in[b * SD + row]);

    while (true) {
        const int snext = s + GRID;
        const bool more = snext < S;
        const int rown  = snext * TPB + d4;

        // Prefetch FIRST: 8 loads issued before any MUFU/store work, so
        // read-issue never pauses at the top of the iteration and the MUFU
        // latency below hides under the in-flight loads.
        float4 N[B];
        if (more) {
            #pragma unroll
            for (int b = 0; b < B; ++b) N[b] = __ldcs(&in[b * SD + rown]);
        }

        const float fs = (float)s;
        float4 pe;                      // d%4==0: x,z even (sin); y,w odd (cos)
        pe.x = __sinf(fs * f0);
        pe.y = __cosf(fs * f1);
        pe.z = __sinf(fs * f2);
        pe.w = __cosf(fs * f3);

        // Store row s (depends only on A, already landed, and pe)
        #pragma unroll
        for (int b = 0; b < B; ++b) {
            float4 o;
            o.x = A[b].x + pe.x; o.y = A[b].y + pe.y;
            o.z = A[b].z + pe.z; o.w = A[b].w + pe.w;
            __stcs(&out[b * SD + row], o);
        }

        if (!more) break;
        #pragma unroll
        for (int b = 0; b < B; ++b) A[b] = N[b];
        s = snext;
        row = rown;
    }
}

extern "C" void kernel_launch(void* const* d_in, const int* in_sizes, int n_in,
                              void* d_out, int out_size) {
    (void)in_sizes; (void)n_in; (void)out_size;
    const float4* in  = (const float4*)d_in[0];
    float4*       out = (float4*)d_out;
    pe_add_kernel<<<GRID, TPB>>>(in, out);
}